// round 1
// baseline (speedup 1.0000x reference)
#include <cuda_runtime.h>
#include <cstdint>

// Problem constants (shapes fixed by the dataset; dims cross-checked at launch
// where cheap): B=64, E=16, D=64, Q_DIM=64, K = D+Q_DIM = 128.
#define B_DIM   64
#define E_DIM   16
#define K_DIM   128
#define BN      64          // n-columns per block
#define PADK    130         // padded row stride (floats) for conflict-free LDS
#define SMEM_BYTES ((B_DIM * PADK + BN * PADK) * 4)

// Scratch: X[b][k] = [ sum_e Z[b,e,k] (k<64) | Q[b][k-64] ]
__device__ float g_X[B_DIM * K_DIM];

// ---------------------------------------------------------------------------
// Kernel A: build X from Z (reduce over E) and Q.
// grid = (64), block = (64): block b, thread d.
__global__ void prep_kernel(const float* __restrict__ Z, const float* __restrict__ Q) {
    int b = blockIdx.x;
    int d = threadIdx.x;
    float s = 0.f;
#pragma unroll
    for (int e = 0; e < E_DIM; ++e)
        s += Z[(b * E_DIM + e) * 64 + d];
    g_X[b * K_DIM + d] = s;
    g_X[b * K_DIM + 64 + d] = Q[b * 64 + d];
}

// ---------------------------------------------------------------------------
// Kernel B: zero V[:, n_np:n_atoms] and set V[:,0] = 1.0
// grid = (ceil(per_row4/256), 64)
__global__ void zero_tail_kernel(float* __restrict__ V, int n_np, int n_atoms) {
    int b = blockIdx.y;
    int per_row4 = (n_atoms - n_np) >> 2;   // tail count divisible by 4 (40000)
    float4 z = make_float4(0.f, 0.f, 0.f, 0.f);
    float4* dst = (float4*)(V + (size_t)b * n_atoms + n_np);
    for (int c = blockIdx.x * blockDim.x + threadIdx.x; c < per_row4;
         c += gridDim.x * blockDim.x)
        dst[c] = z;
    if (blockIdx.x == 0 && threadIdx.x == 0)
        V[(size_t)b * n_atoms] = 1.0f;      // true atom (overwritten if np covers 0)
}

// ---------------------------------------------------------------------------
// Kernel C: scores = sigmoid(X @ [W|U]^T), scattered to V[:, np_idx[n]].
// M=64(b) x N=160000(n) x K=128 SGEMM using packed fma.rn.f32x2.
// block 256 threads -> 64b x 64n tile, 4x4 micro-tile per thread.
__global__ __launch_bounds__(256)
void gemm_kernel(const float* __restrict__ W, const float* __restrict__ U,
                 const int* __restrict__ np_idx, float* __restrict__ V,
                 int n_np, int n_atoms) {
    extern __shared__ float smem[];
    float* Xs = smem;                 // [64][PADK]
    float* Ms = smem + B_DIM * PADK;  // [BN][PADK]

    const int tid = threadIdx.x;
    const int n0  = blockIdx.x * BN;

    // --- load X tile (whole X, padded) ---
#pragma unroll
    for (int idx = tid; idx < B_DIM * K_DIM; idx += 256) {
        int b = idx >> 7, k = idx & 127;
        Xs[b * PADK + k] = g_X[idx];
    }

    // --- load M tile: Ms[r][0:64]=W[n0+r], Ms[r][64:128]=U[n0+r] (float4 reads) ---
#pragma unroll
    for (int idx = tid; idx < BN * 32; idx += 256) {
        int r = idx >> 5, q = idx & 31;
        int n = n0 + r;
        float4 v = make_float4(0.f, 0.f, 0.f, 0.f);
        if (n < n_np)
            v = (q < 16) ? ((const float4*)W)[n * 16 + q]
                         : ((const float4*)U)[n * 16 + (q - 16)];
        int k0 = (q < 16) ? (q * 4) : (64 + (q - 16) * 4);
        float* dst = &Ms[r * PADK + k0];
        dst[0] = v.x; dst[1] = v.y; dst[2] = v.z; dst[3] = v.w;
    }
    __syncthreads();

    const int tx = tid & 15;   // n-group
    const int ty = tid >> 4;   // b-group

    unsigned long long acc[4][4];
#pragma unroll
    for (int i = 0; i < 4; ++i)
#pragma unroll
        for (int j = 0; j < 4; ++j) acc[i][j] = 0ULL;

#pragma unroll 4
    for (int kk = 0; kk < K_DIM / 2; ++kk) {
        unsigned long long x2[4], m2[4];
#pragma unroll
        for (int i = 0; i < 4; ++i)
            x2[i] = *(const unsigned long long*)(Xs + (ty + 16 * i) * PADK + 2 * kk);
#pragma unroll
        for (int j = 0; j < 4; ++j)
            m2[j] = *(const unsigned long long*)(Ms + (tx + 16 * j) * PADK + 2 * kk);
#pragma unroll
        for (int i = 0; i < 4; ++i)
#pragma unroll
            for (int j = 0; j < 4; ++j)
                asm("fma.rn.f32x2 %0, %1, %2, %0;"
                    : "+l"(acc[i][j]) : "l"(x2[i]), "l"(m2[j]));
    }

    // --- epilogue: sigmoid + scatter ---
#pragma unroll
    for (int i = 0; i < 4; ++i) {
        int b = ty + 16 * i;
#pragma unroll
        for (int j = 0; j < 4; ++j) {
            int n = n0 + tx + 16 * j;
            if (n < n_np) {
                float lo = __uint_as_float((unsigned)(acc[i][j] & 0xffffffffULL));
                float hi = __uint_as_float((unsigned)(acc[i][j] >> 32));
                float s  = lo + hi;
                float score = 1.0f / (1.0f + __expf(-s));
                int col = np_idx[n];
                V[(size_t)b * n_atoms + col] = score;
            }
        }
    }
}

// ---------------------------------------------------------------------------
// Kernel D: background-knowledge scatter-add (duplicates must accumulate).
__global__ void bk_add_kernel(float* __restrict__ V, const int* __restrict__ bk,
                              int n_bk, int n_atoms) {
    int t = blockIdx.x * blockDim.x + threadIdx.x;
    if (t < n_bk * B_DIM) {
        int i = t >> 6;           // index into bk
        int b = t & 63;           // batch row
        atomicAdd(V + (size_t)b * n_atoms + bk[i], 1.0f);
    }
}

// ---------------------------------------------------------------------------
extern "C" void kernel_launch(void* const* d_in, const int* in_sizes, int n_in,
                              void* d_out, int out_size) {
    const float* Z      = (const float*)d_in[0];
    const float* Q      = (const float*)d_in[1];
    const float* W      = (const float*)d_in[2];
    const float* U      = (const float*)d_in[3];
    const int*   np_idx = (const int*)d_in[4];
    const int*   bk     = (const int*)d_in[5];
    const int n_np    = in_sizes[4];
    const int n_bk    = in_sizes[5];
    const int n_atoms = out_size / B_DIM;
    float* V = (float*)d_out;

    cudaFuncSetAttribute(gemm_kernel,
                         cudaFuncAttributeMaxDynamicSharedMemorySize, SMEM_BYTES);

    // 1) X = [sum_e Z | Q]
    prep_kernel<<<B_DIM, 64>>>(Z, Q);

    // 2) zero tail region + true atom
    int per_row4 = (n_atoms - n_np) >> 2;
    dim3 zgrid((per_row4 + 255) / 256, B_DIM);
    zero_tail_kernel<<<zgrid, 256>>>(V, n_np, n_atoms);

    // 3) scores GEMM + sigmoid + scatter-set
    int nblocks = (n_np + BN - 1) / BN;
    gemm_kernel<<<nblocks, 256, SMEM_BYTES>>>(W, U, np_idx, V, n_np, n_atoms);

    // 4) bk scatter-add
    int bt = n_bk * B_DIM;
    bk_add_kernel<<<(bt + 255) / 256, 256>>>(V, bk, n_bk, n_atoms);
}

// round 3
// speedup vs baseline: 1.7034x; 1.7034x over previous
#include <cuda_runtime.h>
#include <cuda_fp16.h>
#include <cstdint>

// Shapes fixed by dataset: B=64, E=16, D=64, Q_DIM=64 -> K=128.
#define B_DIM    64
#define K_DIM    128
#define NTILE    128           // W/U rows per tile
#define THREADS  256
#define HIST_CAP 262144

// SMEM layout (bytes)
#define OFF_COLS 0             // 128 ints = 512
#define OFF_XH   512           // 64 x 136 halves = 17408
#define OFF_XL   17920         // 17408
#define OFF_A0   35328         // 128 x 132 floats = 67584
#define OFF_A1   102912        // 67584
#define OFF_STG  170496        // 64 x 130 floats = 33280
#define SMEM_TOTAL 203776

#define XPITCH 136             // halves per X smem row
#define APITCH 132             // floats per A smem row
#define SPITCH 130             // floats per staged row

__device__ __half g_Xh[B_DIM * K_DIM];   // fp16 hi part of [sum_e Z | Q]
__device__ __half g_Xl[B_DIM * K_DIM];   // fp16 residual
__device__ float  g_hist[HIST_CAP];      // per-column bk counts

// ---------------------------------------------------------------------------
__device__ __forceinline__ uint32_t smem_u32(const void* p) {
    uint32_t a;
    asm("{ .reg .u64 t; cvta.to.shared.u64 t, %1; cvt.u32.u64 %0, t; }"
        : "=r"(a) : "l"(p));
    return a;
}

__device__ __forceinline__ uint32_t packh(float lo, float hi) {
    uint32_t r;
    asm("cvt.rn.f16x2.f32 %0, %1, %2;" : "=r"(r) : "f"(hi), "f"(lo));
    return r;
}

__device__ __forceinline__ void mma16816(float* d, uint32_t a0, uint32_t a1,
                                         uint32_t a2, uint32_t a3,
                                         uint32_t b0, uint32_t b1) {
    asm volatile(
        "mma.sync.aligned.m16n8k16.row.col.f32.f16.f16.f32 "
        "{%0,%1,%2,%3}, {%4,%5,%6,%7}, {%8,%9}, {%0,%1,%2,%3};"
        : "+f"(d[0]), "+f"(d[1]), "+f"(d[2]), "+f"(d[3])
        : "r"(a0), "r"(a1), "r"(a2), "r"(a3), "r"(b0), "r"(b1));
}

__device__ __forceinline__ void ldsm4(uint32_t* r, uint32_t addr) {
    asm volatile("ldmatrix.sync.aligned.m8n8.x4.shared.b16 {%0,%1,%2,%3}, [%4];"
                 : "=r"(r[0]), "=r"(r[1]), "=r"(r[2]), "=r"(r[3]) : "r"(addr));
}

__device__ __forceinline__ void load_tile(uint32_t abase,
                                          const float* __restrict__ W,
                                          const float* __restrict__ U,
                                          int n0, int n_np, int tid) {
#pragma unroll
    for (int j = 0; j < 16; ++j) {
        int chunk = tid + THREADS * j;         // 0..4095 (16B chunks)
        int row   = chunk >> 5;                // 0..127
        int kc    = (chunk & 31) << 2;         // float col 0..124
        int n     = n0 + row;
        const float* src = (kc < 64) ? (W + (size_t)n * 64 + kc)
                                     : (U + (size_t)n * 64 + (kc - 64));
        uint32_t dst = abase + row * (APITCH * 4) + kc * 4;
        if (n < n_np)
            asm volatile("cp.async.cg.shared.global [%0], [%1], 16;"
                         :: "r"(dst), "l"(src));
    }
}

// ---------------------------------------------------------------------------
// Persistent HMMA GEMM: scores = sigmoid(Mtile @ X^T) + hist, scatter to V.
__global__ __launch_bounds__(THREADS, 1)
void gemm_kernel(const float* __restrict__ W, const float* __restrict__ U,
                 const int* __restrict__ npi, float* __restrict__ V,
                 int n_np, int n_atoms, int n_tiles) {
    extern __shared__ char smem[];
    const uint32_t sb = smem_u32(smem);
    const int tid = threadIdx.x;
    const int wid = tid >> 5, lane = tid & 31;
    int*    cols   = (int*)(smem + OFF_COLS);
    float*  staged = (float*)(smem + OFF_STG);
    __half* xh_s   = (__half*)(smem + OFF_XH);
    __half* xl_s   = (__half*)(smem + OFF_XL);

    const int bid = blockIdx.x, grid = gridDim.x;
    const int ntl = (n_tiles > bid) ? ((n_tiles - 1 - bid) / grid + 1) : 0;

    if (ntl > 0) {
        load_tile(sb + OFF_A0, W, U, bid * NTILE, n_np, tid);
        asm volatile("cp.async.commit_group;" ::: "memory");
    }

    // X (hi/lo fp16) -> smem, padded rows
    for (int idx = tid; idx < B_DIM * K_DIM; idx += THREADS) {
        int b = idx >> 7, k = idx & 127;
        xh_s[b * XPITCH + k] = g_Xh[idx];
        xl_s[b * XPITCH + k] = g_Xl[idx];
    }

    const int m0 = wid * 16;
    const int qr = lane >> 2, qc = lane & 3;
    const int r0 = m0 + qr, r1 = r0 + 8;
    // ldmatrix lane address components (constant across tiles)
    const int xrow_off = (lane & 7) + ((lane >> 4) << 3);
    const int xcol_off = ((lane >> 3) & 1) * 8;

    for (int i = 0; i < ntl; ++i) {
        const int buf = i & 1;
        const int n0  = (bid + i * grid) * NTILE;

        if (i + 1 < ntl) {
            load_tile(sb + (buf ? OFF_A0 : OFF_A1), W, U,
                      (bid + (i + 1) * grid) * NTILE, n_np, tid);
            asm volatile("cp.async.commit_group;" ::: "memory");
            asm volatile("cp.async.wait_group 1;" ::: "memory");
        } else {
            asm volatile("cp.async.wait_group 0;" ::: "memory");
        }
        if (tid < NTILE) {
            int n = n0 + tid;
            cols[tid] = (n < n_np) ? npi[n] : 0;
        }
        __syncthreads();   // A tile + cols visible; staged/cols safe to reuse

        const float* Ws = (const float*)(smem + (buf ? OFF_A1 : OFF_A0));
        float hv0 = g_hist[cols[r0]];
        float hv1 = g_hist[cols[r1]];

        float d[8][4];
#pragma unroll
        for (int n = 0; n < 8; ++n)
#pragma unroll
            for (int j = 0; j < 4; ++j) d[n][j] = 0.f;

#pragma unroll
        for (int ks = 0; ks < 8; ++ks) {
            const int kk = ks * 16 + 2 * qc;
            float2 w00 = *(const float2*)&Ws[r0 * APITCH + kk];
            float2 w01 = *(const float2*)&Ws[r0 * APITCH + kk + 8];
            float2 w10 = *(const float2*)&Ws[r1 * APITCH + kk];
            float2 w11 = *(const float2*)&Ws[r1 * APITCH + kk + 8];
            uint32_t ah0 = packh(w00.x, w00.y), ah1 = packh(w10.x, w10.y);
            uint32_t ah2 = packh(w01.x, w01.y), ah3 = packh(w11.x, w11.y);
            __half2 h0 = *(__half2*)&ah0, h1 = *(__half2*)&ah1;
            __half2 h2 = *(__half2*)&ah2, h3 = *(__half2*)&ah3;
            uint32_t al0 = packh(w00.x - __low2float(h0), w00.y - __high2float(h0));
            uint32_t al1 = packh(w10.x - __low2float(h1), w10.y - __high2float(h1));
            uint32_t al2 = packh(w01.x - __low2float(h2), w01.y - __high2float(h2));
            uint32_t al3 = packh(w11.x - __low2float(h3), w11.y - __high2float(h3));

#pragma unroll
            for (int nb2 = 0; nb2 < 4; ++nb2) {
                int xoff = ((nb2 * 16 + xrow_off) * XPITCH + ks * 16 + xcol_off) * 2;
                uint32_t bh[4], bl[4];
                ldsm4(bh, sb + OFF_XH + xoff);
                ldsm4(bl, sb + OFF_XL + xoff);
                // pass hh, lh, hl for both n-blocks of this pair
                mma16816(d[2 * nb2],     ah0, ah1, ah2, ah3, bh[0], bh[1]);
                mma16816(d[2 * nb2],     al0, al1, al2, al3, bh[0], bh[1]);
                mma16816(d[2 * nb2],     ah0, ah1, ah2, ah3, bl[0], bl[1]);
                mma16816(d[2 * nb2 + 1], ah0, ah1, ah2, ah3, bh[2], bh[3]);
                mma16816(d[2 * nb2 + 1], al0, al1, al2, al3, bh[2], bh[3]);
                mma16816(d[2 * nb2 + 1], ah0, ah1, ah2, ah3, bl[2], bl[3]);
            }
        }

        // epilogue: sigmoid + hist -> staged[b][n_local]
#pragma unroll
        for (int nb = 0; nb < 8; ++nb) {
#pragma unroll
            for (int j = 0; j < 4; ++j) {
                float s  = d[nb][j];
                float v  = __fdividef(1.0f, 1.0f + __expf(-s)) +
                           ((j >> 1) ? hv1 : hv0);
                int bcol = nb * 8 + 2 * qc + (j & 1);
                int nloc = r0 + ((j >> 1) << 3);
                staged[bcol * SPITCH + nloc] = v;
            }
        }
        __syncthreads();

        // coalesced scatter: V[b][cols[n]]
#pragma unroll
        for (int e = 0; e < 32; ++e) {
            int el = tid + THREADS * e;           // 0..8191
            int bb = el >> 7, nn = el & 127;
            if (n0 + nn < n_np)
                V[(size_t)bb * n_atoms + cols[nn]] = staged[bb * SPITCH + nn];
        }
        __syncthreads();
    }
}

// ---------------------------------------------------------------------------
// prep: X = [sum_e Z | Q], split to fp16 hi/lo; also zero hist.
__global__ void prep_kernel(const float* __restrict__ Z, const float* __restrict__ Q,
                            int n_atoms) {
    if (blockIdx.x < B_DIM) {
        int b = blockIdx.x, k = threadIdx.x;
        if (k < K_DIM) {
            float s;
            if (k < 64) {
                s = 0.f;
#pragma unroll
                for (int e = 0; e < 16; ++e) s += Z[(b * 16 + e) * 64 + k];
            } else {
                s = Q[b * 64 + (k - 64)];
            }
            __half h = __float2half_rn(s);
            g_Xh[b * K_DIM + k] = h;
            g_Xl[b * K_DIM + k] = __float2half_rn(s - __half2float(h));
        }
    } else {
        int idx = (blockIdx.x - B_DIM) * blockDim.x + threadIdx.x;
        int n4 = (n_atoms + 3) >> 2;
        if (idx < n4) ((float4*)g_hist)[idx] = make_float4(0.f, 0.f, 0.f, 0.f);
    }
}

__global__ void hist_kernel(const int* __restrict__ bk, int n_bk) {
    int i = blockIdx.x * blockDim.x + threadIdx.x;
    if (i < n_bk) atomicAdd(&g_hist[bk[i]], 1.0f);
}

// tail: V[b][c] = hist[c] for c in [n_np, n_atoms); V[b][0] = 1 + hist[0]
__global__ void tail_kernel(float* __restrict__ V, int n_np, int n_atoms) {
    int b = blockIdx.y;
    int per4 = (n_atoms - n_np) >> 2;
    int idx = blockIdx.x * blockDim.x + threadIdx.x;
    if (idx < per4) {
        float4 h = ((const float4*)(g_hist + n_np))[idx];
        ((float4*)(V + (size_t)b * n_atoms + n_np))[idx] = h;
    }
    if (blockIdx.x == 0 && threadIdx.x == 0)
        V[(size_t)b * n_atoms] = 1.0f + g_hist[0];
}

// ---------------------------------------------------------------------------
extern "C" void kernel_launch(void* const* d_in, const int* in_sizes, int n_in,
                              void* d_out, int out_size) {
    const float* Z   = (const float*)d_in[0];
    const float* Q   = (const float*)d_in[1];
    const float* W   = (const float*)d_in[2];
    const float* U   = (const float*)d_in[3];
    const int*   npi = (const int*)d_in[4];
    const int*   bk  = (const int*)d_in[5];
    const int n_np    = in_sizes[4];
    const int n_bk    = in_sizes[5];
    const int n_atoms = out_size / B_DIM;
    float* V = (float*)d_out;

    int nsm = 0;
    cudaDeviceGetAttribute(&nsm, cudaDevAttrMultiProcessorCount, 0);
    if (nsm <= 0) nsm = 148;
    cudaFuncSetAttribute(gemm_kernel,
                         cudaFuncAttributeMaxDynamicSharedMemorySize, SMEM_TOTAL);

    int n_tiles = (n_np + NTILE - 1) / NTILE;
    int zb = ((n_atoms + 3) / 4 + 127) / 128;
    prep_kernel<<<B_DIM + zb, 128>>>(Z, Q, n_atoms);
    hist_kernel<<<(n_bk + 255) / 256, 256>>>(bk, n_bk);
    int per4 = (n_atoms - n_np) >> 2;
    dim3 tg((per4 + 255) / 256, B_DIM);
    tail_kernel<<<tg, 256>>>(V, n_np, n_atoms);
    int g = nsm < n_tiles ? nsm : n_tiles;
    gemm_kernel<<<g, THREADS, SMEM_TOTAL>>>(W, U, npi, V, n_np, n_atoms, n_tiles);
}

// round 4
// speedup vs baseline: 1.9154x; 1.1245x over previous
#include <cuda_runtime.h>
#include <cuda_fp16.h>
#include <cstdint>

// Shapes fixed by dataset: B=64, E=16, D=64, Q_DIM=64 -> K=128.
#define B_DIM    64
#define K_DIM    128
#define NTILE    64            // W/U rows per tile
#define THREADS  256
#define HIST_CAP 262144
#define PITCH    136           // halves per smem row (272B = 16B*17: ldsm conflict-free)

// SMEM layout (bytes)
#define OFF_XH   0             // 64 x 136 halves = 17408
#define OFF_XL   17408
#define OFF_A    34816         // 4 x 17408 (Ah0, Al0, Ah1, Al1) = 69632
#define ABUF_SZ  34816         // Ah+Al per buffer
#define AL_DELTA 17408
#define OFF_STG  104448        // 32 x 66 floats = 8448
#define SMEM_TOTAL 112896

__device__ __half g_Xh[B_DIM * K_DIM];   // fp16 hi of [sum_e Z | Q]
__device__ __half g_Xl[B_DIM * K_DIM];   // fp16 residual
__device__ float  g_hist[HIST_CAP];      // per-column bk counts

// ---------------------------------------------------------------------------
__device__ __forceinline__ uint32_t smem_u32(const void* p) {
    uint32_t a;
    asm("{ .reg .u64 t; cvta.to.shared.u64 t, %1; cvt.u32.u64 %0, t; }"
        : "=r"(a) : "l"(p));
    return a;
}

__device__ __forceinline__ uint32_t packh(float lo, float hi) {
    uint32_t r;
    asm("cvt.rn.f16x2.f32 %0, %1, %2;" : "=r"(r) : "f"(hi), "f"(lo));
    return r;
}

__device__ __forceinline__ void mma16816(float* d, const uint32_t* a,
                                         uint32_t b0, uint32_t b1) {
    asm volatile(
        "mma.sync.aligned.m16n8k16.row.col.f32.f16.f16.f32 "
        "{%0,%1,%2,%3}, {%4,%5,%6,%7}, {%8,%9}, {%0,%1,%2,%3};"
        : "+f"(d[0]), "+f"(d[1]), "+f"(d[2]), "+f"(d[3])
        : "r"(a[0]), "r"(a[1]), "r"(a[2]), "r"(a[3]), "r"(b0), "r"(b1));
}

__device__ __forceinline__ void ldsm4(uint32_t* r, uint32_t addr) {
    asm volatile("ldmatrix.sync.aligned.m8n8.x4.shared.b16 {%0,%1,%2,%3}, [%4];"
                 : "=r"(r[0]), "=r"(r[1]), "=r"(r[2]), "=r"(r[3]) : "r"(addr));
}

__device__ __forceinline__ void ldg_tile(float4* pf, const float* __restrict__ W,
                                         const float* __restrict__ U,
                                         int n0, int n_np, int tid) {
#pragma unroll
    for (int j = 0; j < 8; ++j) {
        int chunk = tid + THREADS * j;        // 0..2047 (16B chunks)
        int row   = chunk >> 5;               // 0..63
        int kc    = (chunk & 31) << 2;        // 0..124
        int n     = n0 + row;
        const float* src = (kc < 64) ? (W + (size_t)n * 64 + kc)
                                     : (U + (size_t)n * 64 + (kc - 64));
        if (n < n_np) pf[j] = *(const float4*)src;
    }
}

__device__ __forceinline__ void cvt_sts(const float4* pf, uint32_t ah_base, int tid) {
#pragma unroll
    for (int j = 0; j < 8; ++j) {
        int chunk = tid + THREADS * j;
        int row   = chunk >> 5;
        int kc    = (chunk & 31) << 2;
        float4 v  = pf[j];
        uint32_t h01 = packh(v.x, v.y), h23 = packh(v.z, v.w);
        __half2 H01 = *(__half2*)&h01, H23 = *(__half2*)&h23;
        uint32_t l01 = packh(v.x - __low2float(H01), v.y - __high2float(H01));
        uint32_t l23 = packh(v.z - __low2float(H23), v.w - __high2float(H23));
        uint32_t d = ah_base + (row * PITCH + kc) * 2;
        asm volatile("st.shared.v2.b32 [%0], {%1,%2};" :: "r"(d), "r"(h01), "r"(h23));
        asm volatile("st.shared.v2.b32 [%0], {%1,%2};"
                     :: "r"(d + AL_DELTA), "r"(l01), "r"(l23));
    }
}

// ---------------------------------------------------------------------------
// Persistent HMMA GEMM, 2 CTAs/SM: scores = sigmoid(Wtile @ X^T) + hist -> V.
__global__ __launch_bounds__(THREADS, 2)
void gemm_kernel(const float* __restrict__ W, const float* __restrict__ U,
                 const int* __restrict__ npi, float* __restrict__ V,
                 int n_np, int n_atoms, int n_tiles) {
    extern __shared__ char smem[];
    const uint32_t sb = smem_u32(smem);
    const int tid  = threadIdx.x;
    const int wid  = tid >> 5, lane = tid & 31;
    const int bg   = wid >> 2;              // b-column half (0: 0-31, 1: 32-63)
    const int m0   = (wid & 3) * 16;        // warp's W-row base
    const int qr   = lane >> 2, qc = lane & 3;
    const int r0   = m0 + qr, r1 = r0 + 8;
    float* staged  = (float*)(smem + OFF_STG);

    // X (hi/lo fp16) -> smem (u32 copies), pitch 68 u32
    {
        const uint32_t* gxh = (const uint32_t*)g_Xh;
        const uint32_t* gxl = (const uint32_t*)g_Xl;
        uint32_t* sxh = (uint32_t*)(smem + OFF_XH);
        uint32_t* sxl = (uint32_t*)(smem + OFF_XL);
        for (int idx = tid; idx < 4096; idx += THREADS) {
            int b = idx >> 6, kp = idx & 63;
            sxh[b * 68 + kp] = gxh[idx];
            sxl[b * 68 + kp] = gxl[idx];
        }
    }

    // fragment lane addressing (constant)
    const int arow = (lane & 7) + (((lane >> 3) & 1) << 3);
    const int acol = (lane >> 4) << 3;
    const uint32_t A_off = ((m0 + arow) * PITCH + acol) * 2;
    const int xrow = bg * 32 + (lane & 7) + ((lane >> 4) << 3);
    const int xcol = ((lane >> 3) & 1) << 3;
    const uint32_t Bh0 = sb + OFF_XH + (xrow * PITCH + xcol) * 2;

    const int bid = blockIdx.x, grid = gridDim.x;
    const int ntl = (n_tiles > bid) ? ((n_tiles - 1 - bid) / grid + 1) : 0;

    float4 pf[8];
    if (ntl) {
        ldg_tile(pf, W, U, bid * NTILE, n_np, tid);
        cvt_sts(pf, sb + OFF_A, tid);
    }

    for (int i = 0; i < ntl; ++i) {
        __syncthreads();                      // buf[i&1] visible to all
        const int n0 = (bid + i * grid) * NTILE;
        if (i + 1 < ntl)
            ldg_tile(pf, W, U, (bid + (i + 1) * grid) * NTILE, n_np, tid);

        const int  ncol = n0 + (tid & 63);
        const bool stok = ncol < n_np;
        const int  colv = stok ? npi[ncol] : 0;
        int i0 = n0 + r0; if (i0 >= n_np) i0 = n_np - 1;
        int i1 = n0 + r1; if (i1 >= n_np) i1 = n_np - 1;
        const float hv0 = g_hist[npi[i0]];
        const float hv1 = g_hist[npi[i1]];

        const uint32_t AH = sb + OFF_A + (i & 1) * ABUF_SZ + A_off;
        float d[4][4] = {};
#pragma unroll
        for (int ks = 0; ks < 8; ++ks) {
            uint32_t ah[4], al[4];
            ldsm4(ah, AH + ks * 32);
            ldsm4(al, AH + AL_DELTA + ks * 32);
#pragma unroll
            for (int nb = 0; nb < 2; ++nb) {
                uint32_t bh[4], bl[4];
                uint32_t bb_ = Bh0 + nb * (16 * PITCH * 2) + ks * 32;
                ldsm4(bh, bb_);
                ldsm4(bl, bb_ + AL_DELTA);
                mma16816(d[2 * nb],     ah, bh[0], bh[1]);
                mma16816(d[2 * nb],     al, bh[0], bh[1]);
                mma16816(d[2 * nb],     ah, bl[0], bl[1]);
                mma16816(d[2 * nb + 1], ah, bh[2], bh[3]);
                mma16816(d[2 * nb + 1], al, bh[2], bh[3]);
                mma16816(d[2 * nb + 1], ah, bl[2], bl[3]);
            }
        }

        // epilogue: sigmoid(s) = 0.5 + 0.5*tanh(s/2), + hist; b in two halves
#pragma unroll
        for (int p = 0; p < 2; ++p) {
            if (bg == p) {
#pragma unroll
                for (int nb4 = 0; nb4 < 4; ++nb4)
#pragma unroll
                    for (int j = 0; j < 4; ++j) {
                        float s = d[nb4][j];
                        float t;
                        asm("tanh.approx.f32 %0, %1;" : "=f"(t) : "f"(0.5f * s));
                        float v = fmaf(0.5f, t, 0.5f + ((j >> 1) ? hv1 : hv0));
                        staged[(nb4 * 8 + 2 * qc + (j & 1)) * 66 +
                               r0 + ((j >> 1) << 3)] = v;
                    }
            }
            __syncthreads();
            if (stok) {
#pragma unroll
                for (int e = 0; e < 8; ++e) {
                    int bb = (tid + THREADS * e) >> 6;   // 0..31
                    V[(size_t)(p * 32 + bb) * n_atoms + colv] =
                        staged[bb * 66 + (tid & 63)];
                }
            }
            __syncthreads();
        }

        if (i + 1 < ntl)
            cvt_sts(pf, sb + OFF_A + ((i + 1) & 1) * ABUF_SZ, tid);
    }
}

// ---------------------------------------------------------------------------
// prep: X = [sum_e Z | Q] split to fp16 hi/lo; zero hist.
__global__ void prep_kernel(const float* __restrict__ Z, const float* __restrict__ Q,
                            int n_atoms) {
    if (blockIdx.x < B_DIM) {
        int b = blockIdx.x, k = threadIdx.x;
        if (k < K_DIM) {
            float s;
            if (k < 64) {
                s = 0.f;
#pragma unroll
                for (int e = 0; e < 16; ++e) s += Z[(b * 16 + e) * 64 + k];
            } else {
                s = Q[b * 64 + (k - 64)];
            }
            __half h = __float2half_rn(s);
            g_Xh[b * K_DIM + k] = h;
            g_Xl[b * K_DIM + k] = __float2half_rn(s - __half2float(h));
        }
    } else {
        int idx = (blockIdx.x - B_DIM) * blockDim.x + threadIdx.x;
        int n4 = (n_atoms + 3) >> 2;
        if (idx < n4) ((float4*)g_hist)[idx] = make_float4(0.f, 0.f, 0.f, 0.f);
    }
}

__global__ void hist_kernel(const int* __restrict__ bk, int n_bk) {
    int i = blockIdx.x * blockDim.x + threadIdx.x;
    if (i < n_bk) atomicAdd(&g_hist[bk[i]], 1.0f);
}

// tail: V[b][c] = hist[c] for c in [n_np, n_atoms); V[b][0] = 1 + hist[0]
// (gemm runs after and overwrites col 0 when np_indices covers it — matches ref)
__global__ void tail_kernel(float* __restrict__ V, int n_np, int n_atoms) {
    int b = blockIdx.y;
    int per4 = (n_atoms - n_np) >> 2;
    int idx = blockIdx.x * blockDim.x + threadIdx.x;
    if (idx < per4) {
        float4 h = ((const float4*)(g_hist + n_np))[idx];
        ((float4*)(V + (size_t)b * n_atoms + n_np))[idx] = h;
    }
    if (blockIdx.x == 0 && threadIdx.x == 0)
        V[(size_t)b * n_atoms] = 1.0f + g_hist[0];
}

// ---------------------------------------------------------------------------
extern "C" void kernel_launch(void* const* d_in, const int* in_sizes, int n_in,
                              void* d_out, int out_size) {
    const float* Z   = (const float*)d_in[0];
    const float* Q   = (const float*)d_in[1];
    const float* W   = (const float*)d_in[2];
    const float* U   = (const float*)d_in[3];
    const int*   npi = (const int*)d_in[4];
    const int*   bk  = (const int*)d_in[5];
    const int n_np    = in_sizes[4];
    const int n_bk    = in_sizes[5];
    const int n_atoms = out_size / B_DIM;
    float* V = (float*)d_out;

    int nsm = 0;
    cudaDeviceGetAttribute(&nsm, cudaDevAttrMultiProcessorCount, 0);
    if (nsm <= 0) nsm = 148;
    cudaFuncSetAttribute(gemm_kernel,
                         cudaFuncAttributeMaxDynamicSharedMemorySize, SMEM_TOTAL);

    int n_tiles = (n_np + NTILE - 1) / NTILE;
    int zb = ((n_atoms + 3) / 4 + 127) / 128;
    prep_kernel<<<B_DIM + zb, 128>>>(Z, Q, n_atoms);
    hist_kernel<<<(n_bk + 255) / 256, 256>>>(bk, n_bk);
    int per4 = (n_atoms - n_np) >> 2;
    dim3 tg((per4 + 255) / 256, B_DIM);
    tail_kernel<<<tg, 256>>>(V, n_np, n_atoms);
    int g = 2 * nsm < n_tiles ? 2 * nsm : n_tiles;
    gemm_kernel<<<g, THREADS, SMEM_TOTAL>>>(W, U, npi, V, n_np, n_atoms, n_tiles);
}